// round 15
// baseline (speedup 1.0000x reference)
#include <cuda_runtime.h>
#include <cuda_bf16.h>
#include <math.h>

#define MB 5888
#define VDIM 8150
#define EDIM 300
#define HID 128
#define HX 512
#define TS 46

#define KPAD 8192
#define NPAD 320
#define KPADW 320

// ------------------------- scratch (device globals) ------------------------
static __device__ float g_xz1[MB * HX];
static __device__ float g_xz2[MB * HX];
static __device__ float g_hb1[128 * TS * HID];
static __device__ float g_hb2[128 * TS * HID];
static __device__ float g_ctx1[128 * HID];
static __device__ float g_ctx2[128 * HID];
static __device__ float g_acat[128 * 1024];
static __device__ float g_hidden[128 * 512];
static __device__ __nv_bfloat16 g_bt1h[NPAD * KPAD];
static __device__ __nv_bfloat16 g_bt1l[NPAD * KPAD];
static __device__ __nv_bfloat16 g_bt2h[NPAD * KPAD];
static __device__ __nv_bfloat16 g_bt2l[NPAD * KPAD];
static __device__ __nv_bfloat16 g_wt1h[HX * KPADW];
static __device__ __nv_bfloat16 g_wt1l[HX * KPADW];
static __device__ __nv_bfloat16 g_wt2h[HX * KPADW];
static __device__ __nv_bfloat16 g_wt2l[HX * KPADW];
static __device__ __nv_bfloat16 g_x1h[MB * KPAD];
static __device__ __nv_bfloat16 g_x1l[MB * KPAD];
static __device__ __nv_bfloat16 g_x2h[MB * KPAD];
static __device__ __nv_bfloat16 g_x2l[MB * KPAD];
static __device__ __nv_bfloat16 g_e1h[MB * NPAD];
static __device__ __nv_bfloat16 g_e1l[MB * NPAD];
static __device__ __nv_bfloat16 g_e2h[MB * NPAD];
static __device__ __nv_bfloat16 g_e2l[MB * NPAD];

// ------------------------------ helpers ------------------------------------
__device__ __forceinline__ float wsum(float v) {
#pragma unroll
    for (int o = 16; o > 0; o >>= 1) v += __shfl_xor_sync(0xffffffffu, v, o);
    return v;
}
__device__ __forceinline__ float sigm(float x) { return 1.f / (1.f + expf(-x)); }

__device__ __forceinline__ unsigned smem_u32(const void* p) {
    unsigned a;
    asm("{ .reg .u64 t; cvta.to.shared.u64 t, %1; cvt.u32.u64 %0, t; }" : "=r"(a) : "l"(p));
    return a;
}
__device__ __forceinline__ void ldsm4(unsigned* r, unsigned addr) {
    asm volatile("ldmatrix.sync.aligned.m8n8.x4.shared.b16 {%0,%1,%2,%3}, [%4];"
                 : "=r"(r[0]), "=r"(r[1]), "=r"(r[2]), "=r"(r[3]) : "r"(addr));
}
__device__ __forceinline__ void mma16816(float* c, const unsigned* a, const unsigned* b) {
    asm volatile("mma.sync.aligned.m16n8k16.row.col.f32.bf16.bf16.f32 "
                 "{%0,%1,%2,%3}, {%4,%5,%6,%7}, {%8,%9}, {%0,%1,%2,%3};"
                 : "+f"(c[0]), "+f"(c[1]), "+f"(c[2]), "+f"(c[3])
                 : "r"(a[0]), "r"(a[1]), "r"(a[2]), "r"(a[3]), "r"(b[0]), "r"(b[1]));
}
__device__ __forceinline__ void pack_split(float x, float y, unsigned& hi, unsigned& lo) {
    asm("cvt.rn.bf16x2.f32 %0, %1, %2;" : "=r"(hi) : "f"(y), "f"(x));
    float fx = __uint_as_float(hi << 16);
    float fy = __uint_as_float(hi & 0xffff0000u);
    asm("cvt.rn.bf16x2.f32 %0, %1, %2;" : "=r"(lo) : "f"(y - fy), "f"(x - fx));
}
__device__ __forceinline__ void cpa16(unsigned dst, const void* src) {
    asm volatile("cp.async.ca.shared.global [%0], [%1], 16;" :: "r"(dst), "l"(src));
}

// --------------- prep 1: B-side transpose/split (embed + W_x) ---------------
__global__ void prep_all_k(const float* __restrict__ em1, const float* __restrict__ em2,
                           const float* __restrict__ Wl1, const float* __restrict__ Wl2,
                           __nv_bfloat16* __restrict__ b1h, __nv_bfloat16* __restrict__ b1l,
                           __nv_bfloat16* __restrict__ b2h, __nv_bfloat16* __restrict__ b2l,
                           __nv_bfloat16* __restrict__ w1h, __nv_bfloat16* __restrict__ w1l,
                           __nv_bfloat16* __restrict__ w2h, __nv_bfloat16* __restrict__ w2l)
{
    const int job = blockIdx.z;
    const float* S; int ldsrc, Krows, Ncols, KPo, NPr;
    __nv_bfloat16 *bh, *bl;
    if (job == 0)      { S = em1; ldsrc = EDIM; Krows = VDIM; Ncols = EDIM; KPo = KPAD;  NPr = NPAD; bh = b1h; bl = b1l; }
    else if (job == 1) { S = em2; ldsrc = EDIM; Krows = VDIM; Ncols = EDIM; KPo = KPAD;  NPr = NPAD; bh = b2h; bl = b2l; }
    else if (job == 2) { S = Wl1; ldsrc = HX;   Krows = EDIM; Ncols = HX;   KPo = KPADW; NPr = HX;   bh = w1h; bl = w1l; }
    else               { S = Wl2; ldsrc = HX;   Krows = EDIM; Ncols = HX;   KPo = KPADW; NPr = HX;   bh = w2h; bl = w2l; }

    int k0 = blockIdx.x * 32, n0 = blockIdx.y * 32;
    if (k0 >= KPo || n0 >= NPr) return;

    __shared__ float ts[32][33];
    int tx = threadIdx.x, ty = threadIdx.y;
#pragma unroll
    for (int i = 0; i < 4; i++) {
        int k = k0 + ty + i * 8, n = n0 + tx;
        ts[ty + i * 8][tx] = (k < Krows && n < Ncols) ? S[(size_t)k * ldsrc + n] : 0.f;
    }
    __syncthreads();
#pragma unroll
    for (int i = 0; i < 4; i++) {
        int n = n0 + ty + i * 8, k = k0 + tx;
        if (n < NPr) {
            float v = ts[tx][ty + i * 8];
            __nv_bfloat16 h = __float2bfloat16(v);
            float r = v - __bfloat162float(h);
            bh[(size_t)n * KPo + k] = h;
            bl[(size_t)n * KPo + k] = __float2bfloat16(r);
        }
    }
}

// --------------- prep 2: X fp32 -> bf16 hi/lo, zero-padded to KPAD ----------
__global__ void prep_x_k(const float* __restrict__ x1, const float* __restrict__ x2,
                         __nv_bfloat16* __restrict__ xh1, __nv_bfloat16* __restrict__ xl1,
                         __nv_bfloat16* __restrict__ xh2, __nv_bfloat16* __restrict__ xl2)
{
    const int branch = blockIdx.z;
    const float* x = branch ? x2 : x1;
    __nv_bfloat16* xh = branch ? xh2 : xh1;
    __nv_bfloat16* xl = branch ? xl2 : xl1;
    const int row = blockIdx.y;
    const int k = (blockIdx.x * 256 + threadIdx.x) * 8;
    const float* src = x + (size_t)row * VDIM;
    unsigned h[4], l[4];
    if (k + 8 <= VDIM) {
#pragma unroll
        for (int j = 0; j < 4; j++) {
            float2 v = *reinterpret_cast<const float2*>(src + k + 2 * j);
            pack_split(v.x, v.y, h[j], l[j]);
        }
    } else {
#pragma unroll
        for (int j = 0; j < 4; j++) {
            int kk = k + 2 * j;
            float a = (kk < VDIM) ? src[kk] : 0.f;
            float b = (kk + 1 < VDIM) ? src[kk + 1] : 0.f;
            pack_split(a, b, h[j], l[j]);
        }
    }
    *reinterpret_cast<uint4*>(xh + (size_t)row * KPAD + k) = make_uint4(h[0], h[1], h[2], h[3]);
    *reinterpret_cast<uint4*>(xl + (size_t)row * KPAD + k) = make_uint4(l[0], l[1], l[2], l[3]);
}

// tiny deterministic filler (keeps K1 at launch index 4 for ncu)
__global__ void zero_k(float* __restrict__ p, int n) {
    int i = blockIdx.x * blockDim.x + threadIdx.x;
    if (i < n) p[i] = 0.f;
}

// --------- K1 kernel: BM=128 BN=160, warp 64x80, 2-stage, 1 barrier ---------
// stage (46080B): A part p at p*10240 (128r x 80B); B part p at 20480 + p*12800
#define ST5 46080u
#define HG5_SMEM (2 * 46080)

__global__ void __launch_bounds__(128, 2) hgemm5_k(
    const __nv_bfloat16* __restrict__ A1h, const __nv_bfloat16* __restrict__ A1l,
    const __nv_bfloat16* __restrict__ A2h, const __nv_bfloat16* __restrict__ A2l,
    const __nv_bfloat16* __restrict__ B1h, const __nv_bfloat16* __restrict__ B1l,
    const __nv_bfloat16* __restrict__ B2h, const __nv_bfloat16* __restrict__ B2l,
    __nv_bfloat16* __restrict__ Ch1, __nv_bfloat16* __restrict__ Cl1,
    __nv_bfloat16* __restrict__ Ch2, __nv_bfloat16* __restrict__ Cl2,
    int ldK, int Niter, int ldC)
{
    extern __shared__ char smem[];
    const unsigned sb = smem_u32(smem);
    const int tid = threadIdx.x, wid = tid >> 5, lane = tid & 31;
    const int n0 = blockIdx.x * 160;
    const int m0 = blockIdx.y * 128;
    const int branch = blockIdx.z;

    const __nv_bfloat16* Ah = branch ? A2h : A1h;
    const __nv_bfloat16* Al = branch ? A2l : A1l;
    const __nv_bfloat16* Bh = branch ? B2h : B1h;
    const __nv_bfloat16* Bl = branch ? B2l : B1l;
    __nv_bfloat16* Ch = branch ? Ch2 : Ch1;
    __nv_bfloat16* Cl = branch ? Cl2 : Cl1;

    const int wm = wid >> 1, wn = wid & 1;       // 2x2 warps; tile 64x80
    const int am = lane & 15, ak = (lane >> 4) << 3;
    const int bn = ((lane >> 4) & 1) * 8 + (lane & 7);
    const int bk = ((lane >> 3) & 1) * 8;

    float acc[4][10][4];
#pragma unroll
    for (int mi = 0; mi < 4; mi++)
#pragma unroll
        for (int ni = 0; ni < 10; ni++)
#pragma unroll
            for (int q = 0; q < 4; q++) acc[mi][ni][q] = 0.f;

    auto issue = [&](int ch, int st) {
#pragma unroll
        for (int it = 0; it < 8; it++) {   // A: 1024 x 16B
            int idx = tid + it * 128;
            int p = idx >> 9, rem = idx & 511;
            int row = rem >> 2, u = rem & 3;
            const __nv_bfloat16* src = (p ? Al : Ah) + (size_t)(m0 + row) * ldK + ch * 32 + u * 8;
            cpa16(sb + st * ST5 + p * 10240u + row * 80u + u * 16u, src);
        }
#pragma unroll
        for (int it = 0; it < 10; it++) {  // B: 1280 x 16B (160 rows x 2 parts)
            int idx = tid + it * 128;
            int p = idx / 640, rem = idx - p * 640;
            int row = rem >> 2, u = rem & 3;
            const __nv_bfloat16* src = (p ? Bl : Bh) + (size_t)(n0 + row) * ldK + ch * 32 + u * 8;
            cpa16(sb + st * ST5 + 20480u + p * 12800u + row * 80u + u * 16u, src);
        }
        asm volatile("cp.async.commit_group;");
    };

    issue(0, 0);

    for (int ch = 0; ch < Niter; ch++) {
        asm volatile("cp.async.wait_group 0;");
        __syncthreads();
        if (ch + 1 < Niter) issue(ch + 1, (ch + 1) & 1);

        const unsigned Ab = sb + (ch & 1) * ST5;
        const unsigned Bb = Ab + 20480u;
#pragma unroll
        for (int ks = 0; ks < 2; ks++) {
            unsigned af[2][4][4];
#pragma unroll
            for (int p = 0; p < 2; p++)
#pragma unroll
                for (int mi = 0; mi < 4; mi++)
                    ldsm4(af[p][mi],
                          Ab + p * 10240u + (wm * 64 + mi * 16 + am) * 80u + (ks * 16 + ak) * 2u);
            unsigned bfr[5][4];
            // B part hi: terms Ahi*Bhi and Alo*Bhi
#pragma unroll
            for (int pp = 0; pp < 5; pp++)
                ldsm4(bfr[pp], Bb + (wn * 80 + pp * 16 + bn) * 80u + (ks * 16 + bk) * 2u);
#pragma unroll
            for (int pa = 0; pa < 2; pa++)
#pragma unroll
                for (int mi = 0; mi < 4; mi++)
#pragma unroll
                    for (int ni = 0; ni < 10; ni++)
                        mma16816(acc[mi][ni], af[pa][mi], &bfr[ni >> 1][(ni & 1) * 2]);
            // B part lo: term Ahi*Blo
#pragma unroll
            for (int pp = 0; pp < 5; pp++)
                ldsm4(bfr[pp], Bb + 12800u + (wn * 80 + pp * 16 + bn) * 80u + (ks * 16 + bk) * 2u);
#pragma unroll
            for (int mi = 0; mi < 4; mi++)
#pragma unroll
                for (int ni = 0; ni < 10; ni++)
                    mma16816(acc[mi][ni], af[0][mi], &bfr[ni >> 1][(ni & 1) * 2]);
        }
    }

#pragma unroll
    for (int mi = 0; mi < 4; mi++)
#pragma unroll
        for (int ni = 0; ni < 10; ni++) {
            int col = n0 + wn * 80 + ni * 8 + (lane & 3) * 2;
            int r0 = m0 + wm * 64 + mi * 16 + (lane >> 2);
            unsigned h2, l2;
            pack_split(acc[mi][ni][0], acc[mi][ni][1], h2, l2);
            *reinterpret_cast<unsigned*>(Ch + (size_t)r0 * ldC + col) = h2;
            *reinterpret_cast<unsigned*>(Cl + (size_t)r0 * ldC + col) = l2;
            pack_split(acc[mi][ni][2], acc[mi][ni][3], h2, l2);
            *reinterpret_cast<unsigned*>(Ch + (size_t)(r0 + 8) * ldC + col) = h2;
            *reinterpret_cast<unsigned*>(Cl + (size_t)(r0 + 8) * ldC + col) = l2;
        }
}

// --------- K2 kernel: BM=128 BN=128, warp 64x64 (R13-proven) ----------------
#define ST_BYTES 40960u
#define HG_SMEM (2 * 40960)

__global__ void __launch_bounds__(128, 2) hgemm3_k(
    const __nv_bfloat16* __restrict__ A1h, const __nv_bfloat16* __restrict__ A1l,
    const __nv_bfloat16* __restrict__ A2h, const __nv_bfloat16* __restrict__ A2l,
    const __nv_bfloat16* __restrict__ B1h, const __nv_bfloat16* __restrict__ B1l,
    const __nv_bfloat16* __restrict__ B2h, const __nv_bfloat16* __restrict__ B2l,
    float* __restrict__ Cf1, float* __restrict__ Cf2,
    int ldK, int Niter, int ldC)
{
    extern __shared__ char smem[];
    const unsigned sb = smem_u32(smem);
    const int tid = threadIdx.x, wid = tid >> 5, lane = tid & 31;
    const int n0 = blockIdx.x * 128;
    const int m0 = blockIdx.y * 128;
    const int branch = blockIdx.z;

    const __nv_bfloat16* Ah = branch ? A2h : A1h;
    const __nv_bfloat16* Al = branch ? A2l : A1l;
    const __nv_bfloat16* Bh = branch ? B2h : B1h;
    const __nv_bfloat16* Bl = branch ? B2l : B1l;
    float* Cf = branch ? Cf2 : Cf1;

    const int wm = wid >> 1, wn = wid & 1;
    const int am = lane & 15, ak = (lane >> 4) << 3;
    const int bn = ((lane >> 4) & 1) * 8 + (lane & 7);
    const int bk = ((lane >> 3) & 1) * 8;

    float acc[4][8][4];
#pragma unroll
    for (int mi = 0; mi < 4; mi++)
#pragma unroll
        for (int ni = 0; ni < 8; ni++)
#pragma unroll
            for (int q = 0; q < 4; q++) acc[mi][ni][q] = 0.f;

    auto issue = [&](int ch, int st) {
#pragma unroll
        for (int it = 0; it < 8; it++) {
            int idx = tid + it * 128;
            int p = idx >> 9, rem = idx & 511;
            int row = rem >> 2, u = rem & 3;
            const __nv_bfloat16* src = (p ? Al : Ah) + (size_t)(m0 + row) * ldK + ch * 32 + u * 8;
            cpa16(sb + st * ST_BYTES + p * 10240u + row * 80u + u * 16u, src);
        }
#pragma unroll
        for (int it = 0; it < 8; it++) {
            int idx = tid + it * 128;
            int p = idx >> 9, rem = idx & 511;
            int row = rem >> 2, u = rem & 3;
            const __nv_bfloat16* src = (p ? Bl : Bh) + (size_t)(n0 + row) * ldK + ch * 32 + u * 8;
            cpa16(sb + st * ST_BYTES + 20480u + p * 10240u + row * 80u + u * 16u, src);
        }
        asm volatile("cp.async.commit_group;");
    };

    issue(0, 0);

    for (int ch = 0; ch < Niter; ch++) {
        asm volatile("cp.async.wait_group 0;");
        __syncthreads();
        if (ch + 1 < Niter) issue(ch + 1, (ch + 1) & 1);

        const unsigned Ab = sb + (ch & 1) * ST_BYTES;
        const unsigned Bb = Ab + 20480u;
#pragma unroll
        for (int ks = 0; ks < 2; ks++) {
            unsigned af[2][4][4], bf[2][4][4];
#pragma unroll
            for (int p = 0; p < 2; p++)
#pragma unroll
                for (int mi = 0; mi < 4; mi++)
                    ldsm4(af[p][mi],
                          Ab + p * 10240u + (wm * 64 + mi * 16 + am) * 80u + (ks * 16 + ak) * 2u);
#pragma unroll
            for (int p = 0; p < 2; p++)
#pragma unroll
                for (int pp = 0; pp < 4; pp++)
                    ldsm4(bf[p][pp],
                          Bb + p * 10240u + (wn * 64 + pp * 16 + bn) * 80u + (ks * 16 + bk) * 2u);
#pragma unroll
            for (int s = 0; s < 3; s++) {
                const int pa = (s == 2) ? 1 : 0;
                const int pb = (s == 1) ? 1 : 0;
#pragma unroll
                for (int mi = 0; mi < 4; mi++)
#pragma unroll
                    for (int ni = 0; ni < 8; ni++)
                        mma16816(acc[mi][ni], af[pa][mi], &bf[pb][ni >> 1][(ni & 1) * 2]);
            }
        }
    }

#pragma unroll
    for (int mi = 0; mi < 4; mi++)
#pragma unroll
        for (int ni = 0; ni < 8; ni++) {
            int col = n0 + wn * 64 + ni * 8 + (lane & 3) * 2;
            int r0 = m0 + wm * 64 + mi * 16 + (lane >> 2);
            *reinterpret_cast<float2*>(Cf + (size_t)r0 * ldC + col) =
                make_float2(acc[mi][ni][0], acc[mi][ni][1]);
            *reinterpret_cast<float2*>(Cf + (size_t)(r0 + 8) * ldC + col) =
                make_float2(acc[mi][ni][2], acc[mi][ni][3]);
        }
}

// ---------------- persistent LSTM: 128 CTAs x 2 batch rows (R13) ------------
__global__ __launch_bounds__(512) void lstm_k(
    const float* __restrict__ xz1, const float* __restrict__ xz2,
    const float* __restrict__ W1,  const float* __restrict__ W2,
    const float* __restrict__ lng1, const float* __restrict__ lnb1,
    const float* __restrict__ lng2, const float* __restrict__ lnb2,
    const float* __restrict__ v1,   const float* __restrict__ v2,
    float* __restrict__ hb1, float* __restrict__ hb2,
    float* __restrict__ ctx1, float* __restrict__ ctx2)
{
    __shared__ float h_s[2][HID], c_s[2][HID];
    __shared__ float zpart[4][2][HX];
    __shared__ float lngs[5][HID], lnbs[5][HID], v_s[HID];
    __shared__ float sc[2][TS];
    __shared__ float redA[2][4][4], redA2[2][4][4], redC[2][4][2], redS[2][4];

    const int tid = threadIdx.x;
    const int branch = blockIdx.x >> 6;
    const int b0 = (blockIdx.x & 63) * 2;
    const float* xz  = branch ? xz2 : xz1;
    const float* Wh  = (branch ? W2 : W1) + EDIM * HX;
    const float* lng = branch ? lng2 : lng1;
    const float* lnb = branch ? lnb2 : lnb1;
    const float* vat = branch ? v2 : v1;
    float* hb  = branch ? hb2 : hb1;
    float* ctx = branch ? ctx2 : ctx1;

    if (tid < 2 * HID) { ((float*)h_s)[tid] = 0.f; ((float*)c_s)[tid] = 0.f; }
    for (int i = tid; i < 5 * HID; i += 512) { ((float*)lngs)[i] = lng[i]; ((float*)lnbs)[i] = lnb[i]; }
    if (tid < HID) v_s[tid] = vat[tid];
    __syncthreads();

    const int kp = tid >> 7, jbase = (tid & 127) * 4;
    const int r = tid >> 7, c = tid & 127;
    const int wg = (tid >> 5) & 3, lane = tid & 31;

    for (int t = 0; t < TS; t++) {
        float acc[2][4];
#pragma unroll
        for (int rr = 0; rr < 2; rr++)
#pragma unroll
            for (int j = 0; j < 4; j++) acc[rr][j] = 0.f;
        const float* wp = Wh + (kp * 32) * HX + jbase;
#pragma unroll 4
        for (int kk = 0; kk < 32; kk++) {
            float4 w = *reinterpret_cast<const float4*>(wp + kk * HX);
            int k = kp * 32 + kk;
#pragma unroll
            for (int rr = 0; rr < 2; rr++) {
                float hv = h_s[rr][k];
                acc[rr][0] += hv * w.x; acc[rr][1] += hv * w.y;
                acc[rr][2] += hv * w.z; acc[rr][3] += hv * w.w;
            }
        }
#pragma unroll
        for (int rr = 0; rr < 2; rr++)
            *reinterpret_cast<float4*>(&zpart[kp][rr][jbase]) =
                make_float4(acc[rr][0], acc[rr][1], acc[rr][2], acc[rr][3]);
        __syncthreads();

        float zg[4], gn[4];
        if (r < 2) {
#pragma unroll
            for (int g = 0; g < 4; g++) {
                int col = g * 128 + c;
                zg[g] = xz[((long long)(b0 + r) * TS + t) * HX + col]
                      + zpart[0][r][col] + zpart[1][r][col] + zpart[2][r][col] + zpart[3][r][col];
            }
            float s1[4], s2[4];
#pragma unroll
            for (int g = 0; g < 4; g++) { s1[g] = wsum(zg[g]); s2[g] = wsum(zg[g] * zg[g]); }
            if (lane == 0)
#pragma unroll
                for (int g = 0; g < 4; g++) { redA[r][wg][g] = s1[g]; redA2[r][wg][g] = s2[g]; }
        }
        __syncthreads();
        float cn = 0.f, og = 0.f;
        if (r < 2) {
#pragma unroll
            for (int g = 0; g < 4; g++) {
                float S  = redA[r][0][g] + redA[r][1][g] + redA[r][2][g] + redA[r][3][g];
                float S2 = redA2[r][0][g] + redA2[r][1][g] + redA2[r][2][g] + redA2[r][3][g];
                float mu = S * (1.f / 128.f);
                float var = S2 * (1.f / 128.f) - mu * mu;
                gn[g] = (zg[g] - mu) * rsqrtf(var + 1e-12f) * lngs[g][c] + lnbs[g][c];
            }
            float ig = sigm(gn[0]), jg = fmaxf(gn[1], 0.f);
            float fg = sigm(gn[2] + 1.f);
            og = sigm(gn[3]);
            cn = c_s[r][c] * fg + ig * jg;
            c_s[r][c] = cn;
            float cs1 = wsum(cn), cs2 = wsum(cn * cn);
            if (lane == 0) { redC[r][wg][0] = cs1; redC[r][wg][1] = cs2; }
        }
        __syncthreads();
        if (r < 2) {
            float S  = redC[r][0][0] + redC[r][1][0] + redC[r][2][0] + redC[r][3][0];
            float S2 = redC[r][0][1] + redC[r][1][1] + redC[r][2][1] + redC[r][3][1];
            float mu = S * (1.f / 128.f);
            float var = S2 * (1.f / 128.f) - mu * mu;
            float lnc = (cn - mu) * rsqrtf(var + 1e-12f) * lngs[4][c] + lnbs[4][c];
            float hn = fmaxf(lnc, 0.f) * og;
            h_s[r][c] = hn;
            hb[((long long)(b0 + r) * TS + t) * HID + c] = hn;
            float ss = wsum(hn * v_s[c]);
            if (lane == 0) redS[r][wg] = ss;
        }
        __syncthreads();
        if (r < 2 && c == 0) sc[r][t] = redS[r][0] + redS[r][1] + redS[r][2] + redS[r][3];
        __syncthreads();
    }

    if (r < 2) {
        float mx = -3.0e38f;
#pragma unroll
        for (int t = 0; t < TS; t++) mx = fmaxf(mx, sc[r][t]);
        float den = 0.f, cv = 0.f;
        for (int t = 0; t < TS; t++) {
            float e = expf(sc[r][t] - mx);
            den += e;
            cv += e * hb[((long long)(b0 + r) * TS + t) * HID + c];
        }
        ctx[(b0 + r) * HID + c] = cv / den;
    }
}

// ---------------- fc + relu ------------------------------------------------
__global__ __launch_bounds__(512) void fc_relu_k(const float* __restrict__ in,
                                                 const float* __restrict__ W,
                                                 const float* __restrict__ bias,
                                                 float* __restrict__ out,
                                                 int K, int ldin, int ldout, int ooff)
{
    __shared__ float in_s[4][1024];
    const int tid = threadIdx.x;
    const int r0 = blockIdx.x * 4;
    for (int idx = tid; idx < 4 * K; idx += 512) {
        int rr = idx / K, kk = idx - rr * K;
        in_s[rr][kk] = in[(r0 + rr) * ldin + kk];
    }
    __syncthreads();
    float a[4] = {0.f, 0.f, 0.f, 0.f};
#pragma unroll 4
    for (int k = 0; k < K; k++) {
        float w = W[k * 512 + tid];
#pragma unroll
        for (int rr = 0; rr < 4; rr++) a[rr] += in_s[rr][k] * w;
    }
    float b = bias[tid];
#pragma unroll
    for (int rr = 0; rr < 4; rr++)
        out[(r0 + rr) * ldout + ooff + tid] = fmaxf(a[rr] + b, 0.f);
}

// ---------------- logits ----------------------------------------------------
__global__ __launch_bounds__(64) void logits_k(const float* __restrict__ hid,
                                               const float* __restrict__ W,
                                               const float* __restrict__ b,
                                               float* __restrict__ out)
{
    __shared__ float s0[64], s1[64];
    int r = blockIdx.x, tid = threadIdx.x;
    float a0 = 0.f, a1 = 0.f;
    for (int k = tid; k < 512; k += 64) {
        float h = hid[r * 512 + k];
        a0 += h * W[k * 2];
        a1 += h * W[k * 2 + 1];
    }
    s0[tid] = a0; s1[tid] = a1;
    __syncthreads();
    if (tid < 2) {
        const float* ss = tid ? s1 : s0;
        float s = 0.f;
        for (int i = 0; i < 64; i++) s += ss[i];
        out[r * 2 + tid] = s + b[tid];
    }
}

extern "C" void kernel_launch(void* const* d_in, const int* in_sizes, int n_in,
                              void* d_out, int out_size)
{
    const float* x1   = (const float*)d_in[0];
    const float* x2   = (const float*)d_in[1];
    const float* em1  = (const float*)d_in[2];
    const float* em2  = (const float*)d_in[3];
    const float* Wl1  = (const float*)d_in[4];
    const float* Wl2  = (const float*)d_in[5];
    const float* lng1 = (const float*)d_in[6];
    const float* lnb1 = (const float*)d_in[7];
    const float* lng2 = (const float*)d_in[8];
    const float* lnb2 = (const float*)d_in[9];
    const float* v1   = (const float*)d_in[10];
    const float* Wo1  = (const float*)d_in[11];
    const float* bo1  = (const float*)d_in[12];
    const float* v2   = (const float*)d_in[13];
    const float* Wo2  = (const float*)d_in[14];
    const float* bo2  = (const float*)d_in[15];
    const float* W_h  = (const float*)d_in[16];
    const float* b_h  = (const float*)d_in[17];
    const float* Wout = (const float*)d_in[18];
    const float* bout = (const float*)d_in[19];
    float* out = (float*)d_out;

    float *xz1, *xz2, *hb1, *hb2, *c1, *c2, *acat, *hid;
    __nv_bfloat16 *bt1h, *bt1l, *bt2h, *bt2l, *wt1h, *wt1l, *wt2h, *wt2l;
    __nv_bfloat16 *x1h, *x1l, *x2h, *x2l, *e1h, *e1l, *e2h, *e2l;
    cudaGetSymbolAddress((void**)&xz1, g_xz1);
    cudaGetSymbolAddress((void**)&xz2, g_xz2);
    cudaGetSymbolAddress((void**)&hb1, g_hb1);
    cudaGetSymbolAddress((void**)&hb2, g_hb2);
    cudaGetSymbolAddress((void**)&c1,  g_ctx1);
    cudaGetSymbolAddress((void**)&c2,  g_ctx2);
    cudaGetSymbolAddress((void**)&acat, g_acat);
    cudaGetSymbolAddress((void**)&hid,  g_hidden);
    cudaGetSymbolAddress((void**)&bt1h, g_bt1h);
    cudaGetSymbolAddress((void**)&bt1l, g_bt1l);
    cudaGetSymbolAddress((void**)&bt2h, g_bt2h);
    cudaGetSymbolAddress((void**)&bt2l, g_bt2l);
    cudaGetSymbolAddress((void**)&wt1h, g_wt1h);
    cudaGetSymbolAddress((void**)&wt1l, g_wt1l);
    cudaGetSymbolAddress((void**)&wt2h, g_wt2h);
    cudaGetSymbolAddress((void**)&wt2l, g_wt2l);
    cudaGetSymbolAddress((void**)&x1h, g_x1h);
    cudaGetSymbolAddress((void**)&x1l, g_x1l);
    cudaGetSymbolAddress((void**)&x2h, g_x2h);
    cudaGetSymbolAddress((void**)&x2l, g_x2l);
    cudaGetSymbolAddress((void**)&e1h, g_e1h);
    cudaGetSymbolAddress((void**)&e1l, g_e1l);
    cudaGetSymbolAddress((void**)&e2h, g_e2h);
    cudaGetSymbolAddress((void**)&e2l, g_e2l);

    cudaFuncSetAttribute(hgemm5_k, cudaFuncAttributeMaxDynamicSharedMemorySize, HG5_SMEM);
    cudaFuncSetAttribute(hgemm3_k, cudaFuncAttributeMaxDynamicSharedMemorySize, HG_SMEM);

    // launch 1: B-side prep (embed NPAD=320, W_x KPADW=320)
    prep_all_k<<<dim3(KPAD / 32, 16, 4), dim3(32, 8)>>>(
        em1, em2, Wl1, Wl2, bt1h, bt1l, bt2h, bt2l, wt1h, wt1l, wt2h, wt2l);
    // launch 2: A-side prep
    prep_x_k<<<dim3(KPAD / 2048, MB, 2), 256>>>(x1, x2, x1h, x1l, x2h, x2l);
    // launch 3: filler (acat fully overwritten later)
    zero_k<<<(128 * 1024 + 255) / 256, 256>>>(acat, 128 * 1024);

    // launch 4 (profiled): K1, e = x @ embed, BN=160, bf16 hi/lo out
    hgemm5_k<<<dim3(NPAD / 160, MB / 128, 2), 128, HG5_SMEM>>>(
        x1h, x1l, x2h, x2l, bt1h, bt1l, bt2h, bt2l,
        e1h, e1l, e2h, e2l, KPAD, KPAD / 32, NPAD);

    // launch 5: K2, xz = e @ W_x, fp32 out
    hgemm3_k<<<dim3(HX / 128, MB / 128, 2), 128, HG_SMEM>>>(
        e1h, e1l, e2h, e2l, wt1h, wt1l, wt2h, wt2l,
        xz1, xz2, KPADW, KPADW / 32, HX);

    lstm_k<<<128, 512>>>(xz1, xz2, Wl1, Wl2, lng1, lnb1, lng2, lnb2,
                         v1, v2, hb1, hb2, c1, c2);

    fc_relu_k<<<32, 512>>>(c1, Wo1, bo1, acat, 128, 128, 1024, 0);
    fc_relu_k<<<32, 512>>>(c2, Wo2, bo2, acat, 128, 128, 1024, 512);
    fc_relu_k<<<32, 512>>>(acat, W_h, b_h, hid, 1024, 1024, 512, 0);
    logits_k<<<128, 64>>>(hid, Wout, bout, out);
}

// round 16
// speedup vs baseline: 1.1773x; 1.1773x over previous
#include <cuda_runtime.h>
#include <cuda_bf16.h>
#include <math.h>

#define MB 5888
#define VDIM 8150
#define EDIM 300
#define HID 128
#define HX 512
#define TS 46

#define KPAD 8192
#define NPAD 384
#define KPADW 384

// ------------------------- scratch (device globals) ------------------------
static __device__ float g_xz1[MB * HX];
static __device__ float g_xz2[MB * HX];
static __device__ float g_hb1[128 * TS * HID];
static __device__ float g_hb2[128 * TS * HID];
static __device__ float g_ctx1[128 * HID];
static __device__ float g_ctx2[128 * HID];
static __device__ float g_acat[128 * 1024];
static __device__ float g_hidden[128 * 512];
static __device__ __nv_bfloat16 g_bt1h[NPAD * KPAD];
static __device__ __nv_bfloat16 g_bt1l[NPAD * KPAD];
static __device__ __nv_bfloat16 g_bt2h[NPAD * KPAD];
static __device__ __nv_bfloat16 g_bt2l[NPAD * KPAD];
static __device__ __nv_bfloat16 g_wt1h[HX * KPADW];
static __device__ __nv_bfloat16 g_wt1l[HX * KPADW];
static __device__ __nv_bfloat16 g_wt2h[HX * KPADW];
static __device__ __nv_bfloat16 g_wt2l[HX * KPADW];
static __device__ __nv_bfloat16 g_x1h[MB * KPAD];
static __device__ __nv_bfloat16 g_x1l[MB * KPAD];
static __device__ __nv_bfloat16 g_x2h[MB * KPAD];
static __device__ __nv_bfloat16 g_x2l[MB * KPAD];
static __device__ __nv_bfloat16 g_e1h[MB * NPAD];
static __device__ __nv_bfloat16 g_e1l[MB * NPAD];
static __device__ __nv_bfloat16 g_e2h[MB * NPAD];
static __device__ __nv_bfloat16 g_e2l[MB * NPAD];

// ------------------------------ helpers ------------------------------------
__device__ __forceinline__ float wsum(float v) {
#pragma unroll
    for (int o = 16; o > 0; o >>= 1) v += __shfl_xor_sync(0xffffffffu, v, o);
    return v;
}
__device__ __forceinline__ float sigm(float x) { return 1.f / (1.f + expf(-x)); }

__device__ __forceinline__ unsigned smem_u32(const void* p) {
    unsigned a;
    asm("{ .reg .u64 t; cvta.to.shared.u64 t, %1; cvt.u32.u64 %0, t; }" : "=r"(a) : "l"(p));
    return a;
}
__device__ __forceinline__ void ldsm4(unsigned* r, unsigned addr) {
    asm volatile("ldmatrix.sync.aligned.m8n8.x4.shared.b16 {%0,%1,%2,%3}, [%4];"
                 : "=r"(r[0]), "=r"(r[1]), "=r"(r[2]), "=r"(r[3]) : "r"(addr));
}
__device__ __forceinline__ void mma16816(float* c, const unsigned* a, const unsigned* b) {
    asm volatile("mma.sync.aligned.m16n8k16.row.col.f32.bf16.bf16.f32 "
                 "{%0,%1,%2,%3}, {%4,%5,%6,%7}, {%8,%9}, {%0,%1,%2,%3};"
                 : "+f"(c[0]), "+f"(c[1]), "+f"(c[2]), "+f"(c[3])
                 : "r"(a[0]), "r"(a[1]), "r"(a[2]), "r"(a[3]), "r"(b[0]), "r"(b[1]));
}
__device__ __forceinline__ void pack_split(float x, float y, unsigned& hi, unsigned& lo) {
    asm("cvt.rn.bf16x2.f32 %0, %1, %2;" : "=r"(hi) : "f"(y), "f"(x));
    float fx = __uint_as_float(hi << 16);
    float fy = __uint_as_float(hi & 0xffff0000u);
    asm("cvt.rn.bf16x2.f32 %0, %1, %2;" : "=r"(lo) : "f"(y - fy), "f"(x - fx));
}
__device__ __forceinline__ void cpa16(unsigned dst, const void* src) {
    asm volatile("cp.async.ca.shared.global [%0], [%1], 16;" :: "r"(dst), "l"(src));
}

// ---------- unified prep: 4 transpose/split jobs + 2 X-convert jobs ---------
__global__ void prep_u_k(const float* __restrict__ em1, const float* __restrict__ em2,
                         const float* __restrict__ Wl1, const float* __restrict__ Wl2,
                         const float* __restrict__ x1,  const float* __restrict__ x2,
                         __nv_bfloat16* __restrict__ b1h, __nv_bfloat16* __restrict__ b1l,
                         __nv_bfloat16* __restrict__ b2h, __nv_bfloat16* __restrict__ b2l,
                         __nv_bfloat16* __restrict__ w1h, __nv_bfloat16* __restrict__ w1l,
                         __nv_bfloat16* __restrict__ w2h, __nv_bfloat16* __restrict__ w2l,
                         __nv_bfloat16* __restrict__ xh1, __nv_bfloat16* __restrict__ xl1,
                         __nv_bfloat16* __restrict__ xh2, __nv_bfloat16* __restrict__ xl2)
{
    const int job = blockIdx.z;
    if (job < 4) {
        const float* S; int ldsrc, Krows, Ncols, KPo, NPr;
        __nv_bfloat16 *bh, *bl;
        if (job == 0)      { S = em1; ldsrc = EDIM; Krows = VDIM; Ncols = EDIM; KPo = KPAD;  NPr = NPAD; bh = b1h; bl = b1l; }
        else if (job == 1) { S = em2; ldsrc = EDIM; Krows = VDIM; Ncols = EDIM; KPo = KPAD;  NPr = NPAD; bh = b2h; bl = b2l; }
        else if (job == 2) { S = Wl1; ldsrc = HX;   Krows = EDIM; Ncols = HX;   KPo = KPADW; NPr = HX;   bh = w1h; bl = w1l; }
        else               { S = Wl2; ldsrc = HX;   Krows = EDIM; Ncols = HX;   KPo = KPADW; NPr = HX;   bh = w2h; bl = w2l; }

        int k0 = blockIdx.x * 32, n0 = blockIdx.y * 32;
        if (k0 >= KPo || n0 >= NPr) return;

        __shared__ float ts[32][33];
        int tx = threadIdx.x, ty = threadIdx.y;
#pragma unroll
        for (int i = 0; i < 4; i++) {
            int k = k0 + ty + i * 8, n = n0 + tx;
            ts[ty + i * 8][tx] = (k < Krows && n < Ncols) ? S[(size_t)k * ldsrc + n] : 0.f;
        }
        __syncthreads();
#pragma unroll
        for (int i = 0; i < 4; i++) {
            int n = n0 + ty + i * 8, k = k0 + tx;
            if (n < NPr) {
                float v = ts[tx][ty + i * 8];
                __nv_bfloat16 h = __float2bfloat16(v);
                float r = v - __bfloat162float(h);
                bh[(size_t)n * KPo + k] = h;
                bl[(size_t)n * KPo + k] = __float2bfloat16(r);
            }
        }
    } else {
        // X convert: job 4 -> branch 0, job 5 -> branch 1
        const int branch = job - 4;
        const float* x = branch ? x2 : x1;
        __nv_bfloat16* xh = branch ? xh2 : xh1;
        __nv_bfloat16* xl = branch ? xl2 : xl1;
        const int tid = threadIdx.y * 32 + threadIdx.x;
        const int cta = blockIdx.y * 256 + blockIdx.x;          // 0..4095
        const int stride = 4096 * 256;                           // threads total
        // tasks: MB * (KPAD/8) uint4-groups
        for (int tIdx = cta * 256 + tid; tIdx < MB * (KPAD / 8); tIdx += stride) {
            int row = tIdx >> 10;                // / (KPAD/8 = 1024)
            int k = (tIdx & 1023) * 8;
            const float* src = x + (size_t)row * VDIM;
            unsigned h[4], l[4];
            if (k + 8 <= VDIM) {
#pragma unroll
                for (int j = 0; j < 4; j++) {
                    float2 v = *reinterpret_cast<const float2*>(src + k + 2 * j);
                    pack_split(v.x, v.y, h[j], l[j]);
                }
            } else {
#pragma unroll
                for (int j = 0; j < 4; j++) {
                    int kk = k + 2 * j;
                    float a = (kk < VDIM) ? src[kk] : 0.f;
                    float b = (kk + 1 < VDIM) ? src[kk + 1] : 0.f;
                    pack_split(a, b, h[j], l[j]);
                }
            }
            *reinterpret_cast<uint4*>(xh + (size_t)row * KPAD + k) = make_uint4(h[0], h[1], h[2], h[3]);
            *reinterpret_cast<uint4*>(xl + (size_t)row * KPAD + k) = make_uint4(l[0], l[1], l[2], l[3]);
        }
    }
}

// --------------- pure-bf16 split HMMA GEMM, BM=128 BN=128, warp 64x64 -------
#define ST_BYTES 40960u
#define HG_SMEM (2 * 40960)

__global__ void __launch_bounds__(128, 2) hgemm3_k(
    const __nv_bfloat16* __restrict__ A1h, const __nv_bfloat16* __restrict__ A1l,
    const __nv_bfloat16* __restrict__ A2h, const __nv_bfloat16* __restrict__ A2l,
    const __nv_bfloat16* __restrict__ B1h, const __nv_bfloat16* __restrict__ B1l,
    const __nv_bfloat16* __restrict__ B2h, const __nv_bfloat16* __restrict__ B2l,
    float* __restrict__ Cf1, float* __restrict__ Cf2,
    __nv_bfloat16* __restrict__ Ch1, __nv_bfloat16* __restrict__ Cl1,
    __nv_bfloat16* __restrict__ Ch2, __nv_bfloat16* __restrict__ Cl2,
    int ldK, int Niter, int ldC, int mode)
{
    extern __shared__ char smem[];
    const unsigned sb = smem_u32(smem);
    const int tid = threadIdx.x, wid = tid >> 5, lane = tid & 31;
    const int n0 = blockIdx.x * 128;
    const int m0 = blockIdx.y * 128;
    const int branch = blockIdx.z;

    const __nv_bfloat16* Ah = branch ? A2h : A1h;
    const __nv_bfloat16* Al = branch ? A2l : A1l;
    const __nv_bfloat16* Bh = branch ? B2h : B1h;
    const __nv_bfloat16* Bl = branch ? B2l : B1l;
    float* Cf = branch ? Cf2 : Cf1;
    __nv_bfloat16* Ch = branch ? Ch2 : Ch1;
    __nv_bfloat16* Cl = branch ? Cl2 : Cl1;

    const int wm = wid >> 1, wn = wid & 1;
    const int am = lane & 15, ak = (lane >> 4) << 3;
    const int bn = ((lane >> 4) & 1) * 8 + (lane & 7);
    const int bk = ((lane >> 3) & 1) * 8;

    float acc[4][8][4];
#pragma unroll
    for (int mi = 0; mi < 4; mi++)
#pragma unroll
        for (int ni = 0; ni < 8; ni++)
#pragma unroll
            for (int q = 0; q < 4; q++) acc[mi][ni][q] = 0.f;

    auto issue = [&](int ch, int st) {
#pragma unroll
        for (int it = 0; it < 8; it++) {
            int idx = tid + it * 128;
            int p = idx >> 9, rem = idx & 511;
            int row = rem >> 2, u = rem & 3;
            const __nv_bfloat16* src = (p ? Al : Ah) + (size_t)(m0 + row) * ldK + ch * 32 + u * 8;
            cpa16(sb + st * ST_BYTES + p * 10240u + row * 80u + u * 16u, src);
        }
#pragma unroll
        for (int it = 0; it < 8; it++) {
            int idx = tid + it * 128;
            int p = idx >> 9, rem = idx & 511;
            int row = rem >> 2, u = rem & 3;
            const __nv_bfloat16* src = (p ? Bl : Bh) + (size_t)(n0 + row) * ldK + ch * 32 + u * 8;
            cpa16(sb + st * ST_BYTES + 20480u + p * 10240u + row * 80u + u * 16u, src);
        }
        asm volatile("cp.async.commit_group;");
    };

    issue(0, 0);

    for (int ch = 0; ch < Niter; ch++) {
        asm volatile("cp.async.wait_group 0;");
        __syncthreads();
        if (ch + 1 < Niter) issue(ch + 1, (ch + 1) & 1);

        const unsigned Ab = sb + (ch & 1) * ST_BYTES;
        const unsigned Bb = Ab + 20480u;
#pragma unroll
        for (int ks = 0; ks < 2; ks++) {
            unsigned af[2][4][4], bf[2][4][4];
#pragma unroll
            for (int p = 0; p < 2; p++)
#pragma unroll
                for (int mi = 0; mi < 4; mi++)
                    ldsm4(af[p][mi],
                          Ab + p * 10240u + (wm * 64 + mi * 16 + am) * 80u + (ks * 16 + ak) * 2u);
#pragma unroll
            for (int p = 0; p < 2; p++)
#pragma unroll
                for (int pp = 0; pp < 4; pp++)
                    ldsm4(bf[p][pp],
                          Bb + p * 10240u + (wn * 64 + pp * 16 + bn) * 80u + (ks * 16 + bk) * 2u);
#pragma unroll
            for (int s = 0; s < 3; s++) {
                const int pa = (s == 2) ? 1 : 0;
                const int pb = (s == 1) ? 1 : 0;
#pragma unroll
                for (int mi = 0; mi < 4; mi++)
#pragma unroll
                    for (int ni = 0; ni < 8; ni++)
                        mma16816(acc[mi][ni], af[pa][mi], &bf[pb][ni >> 1][(ni & 1) * 2]);
            }
        }
    }

#pragma unroll
    for (int mi = 0; mi < 4; mi++)
#pragma unroll
        for (int ni = 0; ni < 8; ni++) {
            int col = n0 + wn * 64 + ni * 8 + (lane & 3) * 2;
            int r0 = m0 + wm * 64 + mi * 16 + (lane >> 2);
            if (mode == 0) {
                *reinterpret_cast<float2*>(Cf + (size_t)r0 * ldC + col) =
                    make_float2(acc[mi][ni][0], acc[mi][ni][1]);
                *reinterpret_cast<float2*>(Cf + (size_t)(r0 + 8) * ldC + col) =
                    make_float2(acc[mi][ni][2], acc[mi][ni][3]);
            } else {
                unsigned h2, l2;
                pack_split(acc[mi][ni][0], acc[mi][ni][1], h2, l2);
                *reinterpret_cast<unsigned*>(Ch + (size_t)r0 * ldC + col) = h2;
                *reinterpret_cast<unsigned*>(Cl + (size_t)r0 * ldC + col) = l2;
                pack_split(acc[mi][ni][2], acc[mi][ni][3], h2, l2);
                *reinterpret_cast<unsigned*>(Ch + (size_t)(r0 + 8) * ldC + col) = h2;
                *reinterpret_cast<unsigned*>(Cl + (size_t)(r0 + 8) * ldC + col) = l2;
            }
        }
}

// ---------------- persistent LSTM: 128 CTAs x 2 batch rows ------------------
__global__ __launch_bounds__(512) void lstm_k(
    const float* __restrict__ xz1, const float* __restrict__ xz2,
    const float* __restrict__ W1,  const float* __restrict__ W2,
    const float* __restrict__ lng1, const float* __restrict__ lnb1,
    const float* __restrict__ lng2, const float* __restrict__ lnb2,
    const float* __restrict__ v1,   const float* __restrict__ v2,
    float* __restrict__ hb1, float* __restrict__ hb2,
    float* __restrict__ ctx1, float* __restrict__ ctx2)
{
    __shared__ float h_s[2][HID], c_s[2][HID];
    __shared__ float zpart[4][2][HX];
    __shared__ float lngs[5][HID], lnbs[5][HID], v_s[HID];
    __shared__ float sc[2][TS];
    __shared__ float redA[2][4][4], redA2[2][4][4], redC[2][4][2], redS[2][4];

    const int tid = threadIdx.x;
    const int branch = blockIdx.x >> 6;
    const int b0 = (blockIdx.x & 63) * 2;
    const float* xz  = branch ? xz2 : xz1;
    const float* Wh  = (branch ? W2 : W1) + EDIM * HX;
    const float* lng = branch ? lng2 : lng1;
    const float* lnb = branch ? lnb2 : lnb1;
    const float* vat = branch ? v2 : v1;
    float* hb  = branch ? hb2 : hb1;
    float* ctx = branch ? ctx2 : ctx1;

    if (tid < 2 * HID) { ((float*)h_s)[tid] = 0.f; ((float*)c_s)[tid] = 0.f; }
    for (int i = tid; i < 5 * HID; i += 512) { ((float*)lngs)[i] = lng[i]; ((float*)lnbs)[i] = lnb[i]; }
    if (tid < HID) v_s[tid] = vat[tid];
    __syncthreads();

    const int kp = tid >> 7, jbase = (tid & 127) * 4;
    const int r = tid >> 7, c = tid & 127;
    const int wg = (tid >> 5) & 3, lane = tid & 31;

    for (int t = 0; t < TS; t++) {
        float acc[2][4];
#pragma unroll
        for (int rr = 0; rr < 2; rr++)
#pragma unroll
            for (int j = 0; j < 4; j++) acc[rr][j] = 0.f;
        const float* wp = Wh + (kp * 32) * HX + jbase;
#pragma unroll 4
        for (int kk = 0; kk < 32; kk++) {
            float4 w = *reinterpret_cast<const float4*>(wp + kk * HX);
            int k = kp * 32 + kk;
#pragma unroll
            for (int rr = 0; rr < 2; rr++) {
                float hv = h_s[rr][k];
                acc[rr][0] += hv * w.x; acc[rr][1] += hv * w.y;
                acc[rr][2] += hv * w.z; acc[rr][3] += hv * w.w;
            }
        }
#pragma unroll
        for (int rr = 0; rr < 2; rr++)
            *reinterpret_cast<float4*>(&zpart[kp][rr][jbase]) =
                make_float4(acc[rr][0], acc[rr][1], acc[rr][2], acc[rr][3]);
        __syncthreads();

        float zg[4], gn[4];
        if (r < 2) {
#pragma unroll
            for (int g = 0; g < 4; g++) {
                int col = g * 128 + c;
                zg[g] = xz[((long long)(b0 + r) * TS + t) * HX + col]
                      + zpart[0][r][col] + zpart[1][r][col] + zpart[2][r][col] + zpart[3][r][col];
            }
            float s1[4], s2[4];
#pragma unroll
            for (int g = 0; g < 4; g++) { s1[g] = wsum(zg[g]); s2[g] = wsum(zg[g] * zg[g]); }
            if (lane == 0)
#pragma unroll
                for (int g = 0; g < 4; g++) { redA[r][wg][g] = s1[g]; redA2[r][wg][g] = s2[g]; }
        }
        __syncthreads();
        float cn = 0.f, og = 0.f;
        if (r < 2) {
#pragma unroll
            for (int g = 0; g < 4; g++) {
                float S  = redA[r][0][g] + redA[r][1][g] + redA[r][2][g] + redA[r][3][g];
                float S2 = redA2[r][0][g] + redA2[r][1][g] + redA2[r][2][g] + redA2[r][3][g];
                float mu = S * (1.f / 128.f);
                float var = S2 * (1.f / 128.f) - mu * mu;
                gn[g] = (zg[g] - mu) * rsqrtf(var + 1e-12f) * lngs[g][c] + lnbs[g][c];
            }
            float ig = sigm(gn[0]), jg = fmaxf(gn[1], 0.f);
            float fg = sigm(gn[2] + 1.f);
            og = sigm(gn[3]);
            cn = c_s[r][c] * fg + ig * jg;
            c_s[r][c] = cn;
            float cs1 = wsum(cn), cs2 = wsum(cn * cn);
            if (lane == 0) { redC[r][wg][0] = cs1; redC[r][wg][1] = cs2; }
        }
        __syncthreads();
        if (r < 2) {
            float S  = redC[r][0][0] + redC[r][1][0] + redC[r][2][0] + redC[r][3][0];
            float S2 = redC[r][0][1] + redC[r][1][1] + redC[r][2][1] + redC[r][3][1];
            float mu = S * (1.f / 128.f);
            float var = S2 * (1.f / 128.f) - mu * mu;
            float lnc = (cn - mu) * rsqrtf(var + 1e-12f) * lngs[4][c] + lnbs[4][c];
            float hn = fmaxf(lnc, 0.f) * og;
            h_s[r][c] = hn;
            hb[((long long)(b0 + r) * TS + t) * HID + c] = hn;
            float ss = wsum(hn * v_s[c]);
            if (lane == 0) redS[r][wg] = ss;
        }
        __syncthreads();
        if (r < 2 && c == 0) sc[r][t] = redS[r][0] + redS[r][1] + redS[r][2] + redS[r][3];
        // no trailing barrier: sc writer's redS read completes before next
        // iteration's 3rd barrier releases the next redS writers.
    }
    __syncthreads();   // sc visible to epilogue readers

    if (r < 2) {
        float mx = -3.0e38f;
#pragma unroll
        for (int t = 0; t < TS; t++) mx = fmaxf(mx, sc[r][t]);
        float den = 0.f, cv = 0.f;
        for (int t = 0; t < TS; t++) {
            float e = expf(sc[r][t] - mx);
            den += e;
            cv += e * hb[((long long)(b0 + r) * TS + t) * HID + c];
        }
        ctx[(b0 + r) * HID + c] = cv / den;
    }
}

// ---------------- fc + relu (merged a1+a2 via blockIdx.z) -------------------
__global__ __launch_bounds__(512) void fc_a_k(const float* __restrict__ c1,
                                              const float* __restrict__ c2,
                                              const float* __restrict__ Wo1,
                                              const float* __restrict__ Wo2,
                                              const float* __restrict__ bo1,
                                              const float* __restrict__ bo2,
                                              float* __restrict__ acat)
{
    const int branch = blockIdx.z;
    const float* in  = branch ? c2 : c1;
    const float* W   = branch ? Wo2 : Wo1;
    const float* bia = branch ? bo2 : bo1;
    const int ooff   = branch * 512;

    __shared__ float in_s[4][128];
    const int tid = threadIdx.x;
    const int r0 = blockIdx.x * 4;
    for (int idx = tid; idx < 4 * 128; idx += 512) {
        int rr = idx >> 7, kk = idx & 127;
        in_s[rr][kk] = in[(r0 + rr) * 128 + kk];
    }
    __syncthreads();
    float a[4] = {0.f, 0.f, 0.f, 0.f};
#pragma unroll 4
    for (int k = 0; k < 128; k++) {
        float w = W[k * 512 + tid];
#pragma unroll
        for (int rr = 0; rr < 4; rr++) a[rr] += in_s[rr][k] * w;
    }
    float b = bia[tid];
#pragma unroll
    for (int rr = 0; rr < 4; rr++)
        acat[(r0 + rr) * 1024 + ooff + tid] = fmaxf(a[rr] + b, 0.f);
}

__global__ __launch_bounds__(512) void fc_relu_k(const float* __restrict__ in,
                                                 const float* __restrict__ W,
                                                 const float* __restrict__ bias,
                                                 float* __restrict__ out,
                                                 int K, int ldin, int ldout, int ooff)
{
    __shared__ float in_s[4][1024];
    const int tid = threadIdx.x;
    const int r0 = blockIdx.x * 4;
    for (int idx = tid; idx < 4 * K; idx += 512) {
        int rr = idx / K, kk = idx - rr * K;
        in_s[rr][kk] = in[(r0 + rr) * ldin + kk];
    }
    __syncthreads();
    float a[4] = {0.f, 0.f, 0.f, 0.f};
#pragma unroll 4
    for (int k = 0; k < K; k++) {
        float w = W[k * 512 + tid];
#pragma unroll
        for (int rr = 0; rr < 4; rr++) a[rr] += in_s[rr][k] * w;
    }
    float b = bias[tid];
#pragma unroll
    for (int rr = 0; rr < 4; rr++)
        out[(r0 + rr) * ldout + ooff + tid] = fmaxf(a[rr] + b, 0.f);
}

// ---------------- logits ----------------------------------------------------
__global__ __launch_bounds__(64) void logits_k(const float* __restrict__ hid,
                                               const float* __restrict__ W,
                                               const float* __restrict__ b,
                                               float* __restrict__ out)
{
    __shared__ float s0[64], s1[64];
    int r = blockIdx.x, tid = threadIdx.x;
    float a0 = 0.f, a1 = 0.f;
    for (int k = tid; k < 512; k += 64) {
        float h = hid[r * 512 + k];
        a0 += h * W[k * 2];
        a1 += h * W[k * 2 + 1];
    }
    s0[tid] = a0; s1[tid] = a1;
    __syncthreads();
    if (tid < 2) {
        const float* ss = tid ? s1 : s0;
        float s = 0.f;
        for (int i = 0; i < 64; i++) s += ss[i];
        out[r * 2 + tid] = s + b[tid];
    }
}

extern "C" void kernel_launch(void* const* d_in, const int* in_sizes, int n_in,
                              void* d_out, int out_size)
{
    const float* x1   = (const float*)d_in[0];
    const float* x2   = (const float*)d_in[1];
    const float* em1  = (const float*)d_in[2];
    const float* em2  = (const float*)d_in[3];
    const float* Wl1  = (const float*)d_in[4];
    const float* Wl2  = (const float*)d_in[5];
    const float* lng1 = (const float*)d_in[6];
    const float* lnb1 = (const float*)d_in[7];
    const float* lng2 = (const float*)d_in[8];
    const float* lnb2 = (const float*)d_in[9];
    const float* v1   = (const float*)d_in[10];
    const float* Wo1  = (const float*)d_in[11];
    const float* bo1  = (const float*)d_in[12];
    const float* v2   = (const float*)d_in[13];
    const float* Wo2  = (const float*)d_in[14];
    const float* bo2  = (const float*)d_in[15];
    const float* W_h  = (const float*)d_in[16];
    const float* b_h  = (const float*)d_in[17];
    const float* Wout = (const float*)d_in[18];
    const float* bout = (const float*)d_in[19];
    float* out = (float*)d_out;

    float *xz1, *xz2, *hb1, *hb2, *c1, *c2, *acat, *hid;
    __nv_bfloat16 *bt1h, *bt1l, *bt2h, *bt2l, *wt1h, *wt1l, *wt2h, *wt2l;
    __nv_bfloat16 *x1h, *x1l, *x2h, *x2l, *e1h, *e1l, *e2h, *e2l;
    cudaGetSymbolAddress((void**)&xz1, g_xz1);
    cudaGetSymbolAddress((void**)&xz2, g_xz2);
    cudaGetSymbolAddress((void**)&hb1, g_hb1);
    cudaGetSymbolAddress((void**)&hb2, g_hb2);
    cudaGetSymbolAddress((void**)&c1,  g_ctx1);
    cudaGetSymbolAddress((void**)&c2,  g_ctx2);
    cudaGetSymbolAddress((void**)&acat, g_acat);
    cudaGetSymbolAddress((void**)&hid,  g_hidden);
    cudaGetSymbolAddress((void**)&bt1h, g_bt1h);
    cudaGetSymbolAddress((void**)&bt1l, g_bt1l);
    cudaGetSymbolAddress((void**)&bt2h, g_bt2h);
    cudaGetSymbolAddress((void**)&bt2l, g_bt2l);
    cudaGetSymbolAddress((void**)&wt1h, g_wt1h);
    cudaGetSymbolAddress((void**)&wt1l, g_wt1l);
    cudaGetSymbolAddress((void**)&wt2h, g_wt2h);
    cudaGetSymbolAddress((void**)&wt2l, g_wt2l);
    cudaGetSymbolAddress((void**)&x1h, g_x1h);
    cudaGetSymbolAddress((void**)&x1l, g_x1l);
    cudaGetSymbolAddress((void**)&x2h, g_x2h);
    cudaGetSymbolAddress((void**)&x2l, g_x2l);
    cudaGetSymbolAddress((void**)&e1h, g_e1h);
    cudaGetSymbolAddress((void**)&e1l, g_e1l);
    cudaGetSymbolAddress((void**)&e2h, g_e2h);
    cudaGetSymbolAddress((void**)&e2l, g_e2l);

    cudaFuncSetAttribute(hgemm3_k, cudaFuncAttributeMaxDynamicSharedMemorySize, HG_SMEM);

    // launch 1: unified prep (B-side jobs 0-3, X-convert jobs 4-5)
    prep_u_k<<<dim3(256, 16, 6), dim3(32, 8)>>>(
        em1, em2, Wl1, Wl2, x1, x2,
        bt1h, bt1l, bt2h, bt2l, wt1h, wt1l, wt2h, wt2l,
        x1h, x1l, x2h, x2l);

    // launch 2: K1 merged, e = x @ embed, bf16 hi/lo out
    hgemm3_k<<<dim3(NPAD / 128, MB / 128, 2), 128, HG_SMEM>>>(
        x1h, x1l, x2h, x2l, bt1h, bt1l, bt2h, bt2l,
        (float*)0, (float*)0, e1h, e1l, e2h, e2l,
        KPAD, KPAD / 32, NPAD, 1);

    // launch 3: K2 merged, xz = e @ W_x, fp32 out
    hgemm3_k<<<dim3(HX / 128, MB / 128, 2), 128, HG_SMEM>>>(
        e1h, e1l, e2h, e2l, wt1h, wt1l, wt2h, wt2l,
        xz1, xz2, (__nv_bfloat16*)0, (__nv_bfloat16*)0, (__nv_bfloat16*)0, (__nv_bfloat16*)0,
        KPADW, KPADW / 32, HX, 0);

    // launch 4 (profiled): LSTM recurrence
    lstm_k<<<128, 512>>>(xz1, xz2, Wl1, Wl2, lng1, lnb1, lng2, lnb2,
                         v1, v2, hb1, hb2, c1, c2);

    // launch 5: attention dense (both branches)
    fc_a_k<<<dim3(32, 1, 2), 512>>>(c1, c2, Wo1, Wo2, bo1, bo2, acat);
    // launch 6: hidden dense
    fc_relu_k<<<32, 512>>>(acat, W_h, b_h, hid, 1024, 1024, 512, 0);
    // launch 7: logits
    logits_k<<<128, 64>>>(hid, Wout, bout, out);
}

// round 17
// speedup vs baseline: 1.1972x; 1.0169x over previous
#include <cuda_runtime.h>
#include <cuda_bf16.h>
#include <math.h>

#define MB 5888
#define VDIM 8150
#define EDIM 300
#define HID 128
#define HX 512
#define TS 46

#define KPAD 8192
#define NPAD 384
#define KPADW 384

// ------------------------- scratch (device globals) ------------------------
static __device__ float g_xz1[MB * HX];
static __device__ float g_xz2[MB * HX];
static __device__ float g_hb1[128 * TS * HID];
static __device__ float g_hb2[128 * TS * HID];
static __device__ float g_ctx1[128 * HID];
static __device__ float g_ctx2[128 * HID];
static __device__ float g_acat[128 * 1024];
static __device__ float g_hidden[128 * 512];
static __device__ __nv_bfloat16 g_bt1h[NPAD * KPAD];
static __device__ __nv_bfloat16 g_bt1l[NPAD * KPAD];
static __device__ __nv_bfloat16 g_bt2h[NPAD * KPAD];
static __device__ __nv_bfloat16 g_bt2l[NPAD * KPAD];
static __device__ __nv_bfloat16 g_wt1h[HX * KPADW];
static __device__ __nv_bfloat16 g_wt1l[HX * KPADW];
static __device__ __nv_bfloat16 g_wt2h[HX * KPADW];
static __device__ __nv_bfloat16 g_wt2l[HX * KPADW];
static __device__ __nv_bfloat16 g_x1h[MB * KPAD];
static __device__ __nv_bfloat16 g_x1l[MB * KPAD];
static __device__ __nv_bfloat16 g_x2h[MB * KPAD];
static __device__ __nv_bfloat16 g_x2l[MB * KPAD];
static __device__ __nv_bfloat16 g_e1h[MB * NPAD];
static __device__ __nv_bfloat16 g_e1l[MB * NPAD];
static __device__ __nv_bfloat16 g_e2h[MB * NPAD];
static __device__ __nv_bfloat16 g_e2l[MB * NPAD];

// ------------------------------ helpers ------------------------------------
__device__ __forceinline__ float wsum(float v) {
#pragma unroll
    for (int o = 16; o > 0; o >>= 1) v += __shfl_xor_sync(0xffffffffu, v, o);
    return v;
}
__device__ __forceinline__ float sigm(float x) { return 1.f / (1.f + expf(-x)); }

__device__ __forceinline__ unsigned smem_u32(const void* p) {
    unsigned a;
    asm("{ .reg .u64 t; cvta.to.shared.u64 t, %1; cvt.u32.u64 %0, t; }" : "=r"(a) : "l"(p));
    return a;
}
__device__ __forceinline__ void ldsm4(unsigned* r, unsigned addr) {
    asm volatile("ldmatrix.sync.aligned.m8n8.x4.shared.b16 {%0,%1,%2,%3}, [%4];"
                 : "=r"(r[0]), "=r"(r[1]), "=r"(r[2]), "=r"(r[3]) : "r"(addr));
}
__device__ __forceinline__ void mma16816(float* c, const unsigned* a, const unsigned* b) {
    asm volatile("mma.sync.aligned.m16n8k16.row.col.f32.bf16.bf16.f32 "
                 "{%0,%1,%2,%3}, {%4,%5,%6,%7}, {%8,%9}, {%0,%1,%2,%3};"
                 : "+f"(c[0]), "+f"(c[1]), "+f"(c[2]), "+f"(c[3])
                 : "r"(a[0]), "r"(a[1]), "r"(a[2]), "r"(a[3]), "r"(b[0]), "r"(b[1]));
}
__device__ __forceinline__ void pack_split(float x, float y, unsigned& hi, unsigned& lo) {
    asm("cvt.rn.bf16x2.f32 %0, %1, %2;" : "=r"(hi) : "f"(y), "f"(x));
    float fx = __uint_as_float(hi << 16);
    float fy = __uint_as_float(hi & 0xffff0000u);
    asm("cvt.rn.bf16x2.f32 %0, %1, %2;" : "=r"(lo) : "f"(y - fy), "f"(x - fx));
}
__device__ __forceinline__ void cpa16(unsigned dst, const void* src) {
    asm volatile("cp.async.ca.shared.global [%0], [%1], 16;" :: "r"(dst), "l"(src));
}

// ---------- unified prep: 4 transpose/split jobs + 2 X-convert jobs ---------
__global__ void prep_u_k(const float* __restrict__ em1, const float* __restrict__ em2,
                         const float* __restrict__ Wl1, const float* __restrict__ Wl2,
                         const float* __restrict__ x1,  const float* __restrict__ x2,
                         __nv_bfloat16* __restrict__ b1h, __nv_bfloat16* __restrict__ b1l,
                         __nv_bfloat16* __restrict__ b2h, __nv_bfloat16* __restrict__ b2l,
                         __nv_bfloat16* __restrict__ w1h, __nv_bfloat16* __restrict__ w1l,
                         __nv_bfloat16* __restrict__ w2h, __nv_bfloat16* __restrict__ w2l,
                         __nv_bfloat16* __restrict__ xh1, __nv_bfloat16* __restrict__ xl1,
                         __nv_bfloat16* __restrict__ xh2, __nv_bfloat16* __restrict__ xl2)
{
    const int job = blockIdx.z;
    if (job < 4) {
        const float* S; int ldsrc, Krows, Ncols, KPo, NPr;
        __nv_bfloat16 *bh, *bl;
        if (job == 0)      { S = em1; ldsrc = EDIM; Krows = VDIM; Ncols = EDIM; KPo = KPAD;  NPr = NPAD; bh = b1h; bl = b1l; }
        else if (job == 1) { S = em2; ldsrc = EDIM; Krows = VDIM; Ncols = EDIM; KPo = KPAD;  NPr = NPAD; bh = b2h; bl = b2l; }
        else if (job == 2) { S = Wl1; ldsrc = HX;   Krows = EDIM; Ncols = HX;   KPo = KPADW; NPr = HX;   bh = w1h; bl = w1l; }
        else               { S = Wl2; ldsrc = HX;   Krows = EDIM; Ncols = HX;   KPo = KPADW; NPr = HX;   bh = w2h; bl = w2l; }

        int k0 = blockIdx.x * 32, n0 = blockIdx.y * 32;
        if (k0 >= KPo || n0 >= NPr) return;

        __shared__ float ts[32][33];
        int tx = threadIdx.x, ty = threadIdx.y;
#pragma unroll
        for (int i = 0; i < 4; i++) {
            int k = k0 + ty + i * 8, n = n0 + tx;
            ts[ty + i * 8][tx] = (k < Krows && n < Ncols) ? S[(size_t)k * ldsrc + n] : 0.f;
        }
        __syncthreads();
#pragma unroll
        for (int i = 0; i < 4; i++) {
            int n = n0 + ty + i * 8, k = k0 + tx;
            if (n < NPr) {
                float v = ts[tx][ty + i * 8];
                __nv_bfloat16 h = __float2bfloat16(v);
                float r = v - __bfloat162float(h);
                bh[(size_t)n * KPo + k] = h;
                bl[(size_t)n * KPo + k] = __float2bfloat16(r);
            }
        }
    } else {
        const int branch = job - 4;
        const float* x = branch ? x2 : x1;
        __nv_bfloat16* xh = branch ? xh2 : xh1;
        __nv_bfloat16* xl = branch ? xl2 : xl1;
        const int tid = threadIdx.y * 32 + threadIdx.x;
        const int cta = blockIdx.y * 256 + blockIdx.x;
        const int stride = 4096 * 256;
        for (int tIdx = cta * 256 + tid; tIdx < MB * (KPAD / 8); tIdx += stride) {
            int row = tIdx >> 10;
            int k = (tIdx & 1023) * 8;
            const float* src = x + (size_t)row * VDIM;
            unsigned h[4], l[4];
            if (k + 8 <= VDIM) {
#pragma unroll
                for (int j = 0; j < 4; j++) {
                    float2 v = *reinterpret_cast<const float2*>(src + k + 2 * j);
                    pack_split(v.x, v.y, h[j], l[j]);
                }
            } else {
#pragma unroll
                for (int j = 0; j < 4; j++) {
                    int kk = k + 2 * j;
                    float a = (kk < VDIM) ? src[kk] : 0.f;
                    float b = (kk + 1 < VDIM) ? src[kk + 1] : 0.f;
                    pack_split(a, b, h[j], l[j]);
                }
            }
            *reinterpret_cast<uint4*>(xh + (size_t)row * KPAD + k) = make_uint4(h[0], h[1], h[2], h[3]);
            *reinterpret_cast<uint4*>(xl + (size_t)row * KPAD + k) = make_uint4(l[0], l[1], l[2], l[3]);
        }
    }
}

// --------------- pure-bf16 split HMMA GEMM, BM=128 BN=128, warp 64x64 -------
#define ST_BYTES 40960u
#define HG_SMEM (2 * 40960)

__global__ void __launch_bounds__(128, 2) hgemm3_k(
    const __nv_bfloat16* __restrict__ A1h, const __nv_bfloat16* __restrict__ A1l,
    const __nv_bfloat16* __restrict__ A2h, const __nv_bfloat16* __restrict__ A2l,
    const __nv_bfloat16* __restrict__ B1h, const __nv_bfloat16* __restrict__ B1l,
    const __nv_bfloat16* __restrict__ B2h, const __nv_bfloat16* __restrict__ B2l,
    float* __restrict__ Cf1, float* __restrict__ Cf2,
    __nv_bfloat16* __restrict__ Ch1, __nv_bfloat16* __restrict__ Cl1,
    __nv_bfloat16* __restrict__ Ch2, __nv_bfloat16* __restrict__ Cl2,
    int ldK, int Niter, int ldC, int mode)
{
    extern __shared__ char smem[];
    const unsigned sb = smem_u32(smem);
    const int tid = threadIdx.x, wid = tid >> 5, lane = tid & 31;
    const int n0 = blockIdx.x * 128;
    const int m0 = blockIdx.y * 128;
    const int branch = blockIdx.z;

    const __nv_bfloat16* Ah = branch ? A2h : A1h;
    const __nv_bfloat16* Al = branch ? A2l : A1l;
    const __nv_bfloat16* Bh = branch ? B2h : B1h;
    const __nv_bfloat16* Bl = branch ? B2l : B1l;
    float* Cf = branch ? Cf2 : Cf1;
    __nv_bfloat16* Ch = branch ? Ch2 : Ch1;
    __nv_bfloat16* Cl = branch ? Cl2 : Cl1;

    const int wm = wid >> 1, wn = wid & 1;
    const int am = lane & 15, ak = (lane >> 4) << 3;
    const int bn = ((lane >> 4) & 1) * 8 + (lane & 7);
    const int bk = ((lane >> 3) & 1) * 8;

    float acc[4][8][4];
#pragma unroll
    for (int mi = 0; mi < 4; mi++)
#pragma unroll
        for (int ni = 0; ni < 8; ni++)
#pragma unroll
            for (int q = 0; q < 4; q++) acc[mi][ni][q] = 0.f;

    auto issue = [&](int ch, int st) {
#pragma unroll
        for (int it = 0; it < 8; it++) {
            int idx = tid + it * 128;
            int p = idx >> 9, rem = idx & 511;
            int row = rem >> 2, u = rem & 3;
            const __nv_bfloat16* src = (p ? Al : Ah) + (size_t)(m0 + row) * ldK + ch * 32 + u * 8;
            cpa16(sb + st * ST_BYTES + p * 10240u + row * 80u + u * 16u, src);
        }
#pragma unroll
        for (int it = 0; it < 8; it++) {
            int idx = tid + it * 128;
            int p = idx >> 9, rem = idx & 511;
            int row = rem >> 2, u = rem & 3;
            const __nv_bfloat16* src = (p ? Bl : Bh) + (size_t)(n0 + row) * ldK + ch * 32 + u * 8;
            cpa16(sb + st * ST_BYTES + 20480u + p * 10240u + row * 80u + u * 16u, src);
        }
        asm volatile("cp.async.commit_group;");
    };

    issue(0, 0);

    for (int ch = 0; ch < Niter; ch++) {
        asm volatile("cp.async.wait_group 0;");
        __syncthreads();
        if (ch + 1 < Niter) issue(ch + 1, (ch + 1) & 1);

        const unsigned Ab = sb + (ch & 1) * ST_BYTES;
        const unsigned Bb = Ab + 20480u;
#pragma unroll
        for (int ks = 0; ks < 2; ks++) {
            unsigned af[2][4][4], bf[2][4][4];
#pragma unroll
            for (int p = 0; p < 2; p++)
#pragma unroll
                for (int mi = 0; mi < 4; mi++)
                    ldsm4(af[p][mi],
                          Ab + p * 10240u + (wm * 64 + mi * 16 + am) * 80u + (ks * 16 + ak) * 2u);
#pragma unroll
            for (int p = 0; p < 2; p++)
#pragma unroll
                for (int pp = 0; pp < 4; pp++)
                    ldsm4(bf[p][pp],
                          Bb + p * 10240u + (wn * 64 + pp * 16 + bn) * 80u + (ks * 16 + bk) * 2u);
#pragma unroll
            for (int s = 0; s < 3; s++) {
                const int pa = (s == 2) ? 1 : 0;
                const int pb = (s == 1) ? 1 : 0;
#pragma unroll
                for (int mi = 0; mi < 4; mi++)
#pragma unroll
                    for (int ni = 0; ni < 8; ni++)
                        mma16816(acc[mi][ni], af[pa][mi], &bf[pb][ni >> 1][(ni & 1) * 2]);
            }
        }
    }

#pragma unroll
    for (int mi = 0; mi < 4; mi++)
#pragma unroll
        for (int ni = 0; ni < 8; ni++) {
            int col = n0 + wn * 64 + ni * 8 + (lane & 3) * 2;
            int r0 = m0 + wm * 64 + mi * 16 + (lane >> 2);
            if (mode == 0) {
                *reinterpret_cast<float2*>(Cf + (size_t)r0 * ldC + col) =
                    make_float2(acc[mi][ni][0], acc[mi][ni][1]);
                *reinterpret_cast<float2*>(Cf + (size_t)(r0 + 8) * ldC + col) =
                    make_float2(acc[mi][ni][2], acc[mi][ni][3]);
            } else {
                unsigned h2, l2;
                pack_split(acc[mi][ni][0], acc[mi][ni][1], h2, l2);
                *reinterpret_cast<unsigned*>(Ch + (size_t)r0 * ldC + col) = h2;
                *reinterpret_cast<unsigned*>(Cl + (size_t)r0 * ldC + col) = l2;
                pack_split(acc[mi][ni][2], acc[mi][ni][3], h2, l2);
                *reinterpret_cast<unsigned*>(Ch + (size_t)(r0 + 8) * ldC + col) = h2;
                *reinterpret_cast<unsigned*>(Cl + (size_t)(r0 + 8) * ldC + col) = l2;
            }
        }
}

// ------ persistent LSTM: 128 CTAs x 2 rows; MLP-8 pipelined phase A ---------
__global__ __launch_bounds__(512) void lstm_k(
    const float* __restrict__ xz1, const float* __restrict__ xz2,
    const float* __restrict__ W1,  const float* __restrict__ W2,
    const float* __restrict__ lng1, const float* __restrict__ lnb1,
    const float* __restrict__ lng2, const float* __restrict__ lnb2,
    const float* __restrict__ v1,   const float* __restrict__ v2,
    float* __restrict__ hb1, float* __restrict__ hb2,
    float* __restrict__ ctx1, float* __restrict__ ctx2)
{
    __shared__ float h_s[2][HID], c_s[2][HID];
    __shared__ float zpart[4][2][HX];
    __shared__ float lngs[5][HID], lnbs[5][HID], v_s[HID];
    __shared__ float sc[2][TS];
    __shared__ float redA[2][4][4], redA2[2][4][4], redC[2][4][2], redS[2][4];

    const int tid = threadIdx.x;
    const int branch = blockIdx.x >> 6;
    const int b0 = (blockIdx.x & 63) * 2;
    const float* xz  = branch ? xz2 : xz1;
    const float* Wh  = (branch ? W2 : W1) + EDIM * HX;
    const float* lng = branch ? lng2 : lng1;
    const float* lnb = branch ? lnb2 : lnb1;
    const float* vat = branch ? v2 : v1;
    float* hb  = branch ? hb2 : hb1;
    float* ctx = branch ? ctx2 : ctx1;

    if (tid < 2 * HID) { ((float*)h_s)[tid] = 0.f; ((float*)c_s)[tid] = 0.f; }
    for (int i = tid; i < 5 * HID; i += 512) { ((float*)lngs)[i] = lng[i]; ((float*)lnbs)[i] = lnb[i]; }
    if (tid < HID) v_s[tid] = vat[tid];
    __syncthreads();

    const int kp = tid >> 7, jbase = (tid & 127) * 4;
    const int r = tid >> 7, c = tid & 127;
    const int wg = (tid >> 5) & 3, lane = tid & 31;
    const float* wp = Wh + (kp * 32) * HX + jbase;

    for (int t = 0; t < TS; t++) {
        // prefetch xz early (hides L2/DRAM latency under phase A)
        float xzv[4];
        if (r < 2) {
#pragma unroll
            for (int g = 0; g < 4; g++)
                xzv[g] = xz[((long long)(b0 + r) * TS + t) * HX + g * 128 + c];
        }

        // phase A: z_h = h @ W_h, chunked MLP-8 double-buffered loads
        float acc[2][4];
#pragma unroll
        for (int rr = 0; rr < 2; rr++)
#pragma unroll
            for (int j = 0; j < 4; j++) acc[rr][j] = 0.f;

        float4 wcur[8], wnxt[8];
#pragma unroll
        for (int i = 0; i < 8; i++)
            wcur[i] = *reinterpret_cast<const float4*>(wp + i * HX);
#pragma unroll
        for (int chunk = 0; chunk < 4; chunk++) {
            if (chunk < 3) {
#pragma unroll
                for (int i = 0; i < 8; i++)
                    wnxt[i] = *reinterpret_cast<const float4*>(wp + ((chunk + 1) * 8 + i) * HX);
            }
            const int kb = kp * 32 + chunk * 8;
            float4 h0a = *reinterpret_cast<const float4*>(&h_s[0][kb]);
            float4 h0b = *reinterpret_cast<const float4*>(&h_s[0][kb + 4]);
            float4 h1a = *reinterpret_cast<const float4*>(&h_s[1][kb]);
            float4 h1b = *reinterpret_cast<const float4*>(&h_s[1][kb + 4]);
            float h0[8] = {h0a.x, h0a.y, h0a.z, h0a.w, h0b.x, h0b.y, h0b.z, h0b.w};
            float h1[8] = {h1a.x, h1a.y, h1a.z, h1a.w, h1b.x, h1b.y, h1b.z, h1b.w};
#pragma unroll
            for (int i = 0; i < 8; i++) {
                float4 w = wcur[i];
                acc[0][0] += h0[i] * w.x; acc[0][1] += h0[i] * w.y;
                acc[0][2] += h0[i] * w.z; acc[0][3] += h0[i] * w.w;
                acc[1][0] += h1[i] * w.x; acc[1][1] += h1[i] * w.y;
                acc[1][2] += h1[i] * w.z; acc[1][3] += h1[i] * w.w;
            }
            if (chunk < 3) {
#pragma unroll
                for (int i = 0; i < 8; i++) wcur[i] = wnxt[i];
            }
        }
#pragma unroll
        for (int rr = 0; rr < 2; rr++)
            *reinterpret_cast<float4*>(&zpart[kp][rr][jbase]) =
                make_float4(acc[rr][0], acc[rr][1], acc[rr][2], acc[rr][3]);
        __syncthreads();

        float zg[4], gn[4];
        if (r < 2) {
#pragma unroll
            for (int g = 0; g < 4; g++) {
                int col = g * 128 + c;
                zg[g] = xzv[g]
                      + zpart[0][r][col] + zpart[1][r][col] + zpart[2][r][col] + zpart[3][r][col];
            }
            float s1[4], s2[4];
#pragma unroll
            for (int g = 0; g < 4; g++) { s1[g] = wsum(zg[g]); s2[g] = wsum(zg[g] * zg[g]); }
            if (lane == 0)
#pragma unroll
                for (int g = 0; g < 4; g++) { redA[r][wg][g] = s1[g]; redA2[r][wg][g] = s2[g]; }
        }
        __syncthreads();
        float cn = 0.f, og = 0.f;
        if (r < 2) {
#pragma unroll
            for (int g = 0; g < 4; g++) {
                float S  = redA[r][0][g] + redA[r][1][g] + redA[r][2][g] + redA[r][3][g];
                float S2 = redA2[r][0][g] + redA2[r][1][g] + redA2[r][2][g] + redA2[r][3][g];
                float mu = S * (1.f / 128.f);
                float var = S2 * (1.f / 128.f) - mu * mu;
                gn[g] = (zg[g] - mu) * rsqrtf(var + 1e-12f) * lngs[g][c] + lnbs[g][c];
            }
            float ig = sigm(gn[0]), jg = fmaxf(gn[1], 0.f);
            float fg = sigm(gn[2] + 1.f);
            og = sigm(gn[3]);
            cn = c_s[r][c] * fg + ig * jg;
            c_s[r][c] = cn;
            float cs1 = wsum(cn), cs2 = wsum(cn * cn);
            if (lane == 0) { redC[r][wg][0] = cs1; redC[r][wg][1] = cs2; }
        }
        __syncthreads();
        if (r < 2) {
            float S  = redC[r][0][0] + redC[r][1][0] + redC[r][2][0] + redC[r][3][0];
            float S2 = redC[r][0][1] + redC[r][1][1] + redC[r][2][1] + redC[r][3][1];
            float mu = S * (1.f / 128.f);
            float var = S2 * (1.f / 128.f) - mu * mu;
            float lnc = (cn - mu) * rsqrtf(var + 1e-12f) * lngs[4][c] + lnbs[4][c];
            float hn = fmaxf(lnc, 0.f) * og;
            h_s[r][c] = hn;
            hb[((long long)(b0 + r) * TS + t) * HID + c] = hn;
            float ss = wsum(hn * v_s[c]);
            if (lane == 0) redS[r][wg] = ss;
        }
        __syncthreads();
        if (r < 2 && c == 0) sc[r][t] = redS[r][0] + redS[r][1] + redS[r][2] + redS[r][3];
    }
    __syncthreads();

    if (r < 2) {
        float mx = -3.0e38f;
#pragma unroll
        for (int t = 0; t < TS; t++) mx = fmaxf(mx, sc[r][t]);
        float den = 0.f, cv = 0.f;
        for (int t = 0; t < TS; t++) {
            float e = expf(sc[r][t] - mx);
            den += e;
            cv += e * hb[((long long)(b0 + r) * TS + t) * HID + c];
        }
        ctx[(b0 + r) * HID + c] = cv / den;
    }
}

// ---------------- fc + relu (merged a1+a2 via blockIdx.z) -------------------
__global__ __launch_bounds__(512) void fc_a_k(const float* __restrict__ c1,
                                              const float* __restrict__ c2,
                                              const float* __restrict__ Wo1,
                                              const float* __restrict__ Wo2,
                                              const float* __restrict__ bo1,
                                              const float* __restrict__ bo2,
                                              float* __restrict__ acat)
{
    const int branch = blockIdx.z;
    const float* in  = branch ? c2 : c1;
    const float* W   = branch ? Wo2 : Wo1;
    const float* bia = branch ? bo2 : bo1;
    const int ooff   = branch * 512;

    __shared__ float in_s[4][128];
    const int tid = threadIdx.x;
    const int r0 = blockIdx.x * 4;
    for (int idx = tid; idx < 4 * 128; idx += 512) {
        int rr = idx >> 7, kk = idx & 127;
        in_s[rr][kk] = in[(r0 + rr) * 128 + kk];
    }
    __syncthreads();
    float a[4] = {0.f, 0.f, 0.f, 0.f};
#pragma unroll 4
    for (int k = 0; k < 128; k++) {
        float w = W[k * 512 + tid];
#pragma unroll
        for (int rr = 0; rr < 4; rr++) a[rr] += in_s[rr][k] * w;
    }
    float b = bia[tid];
#pragma unroll
    for (int rr = 0; rr < 4; rr++)
        acat[(r0 + rr) * 1024 + ooff + tid] = fmaxf(a[rr] + b, 0.f);
}

__global__ __launch_bounds__(512) void fc_relu_k(const float* __restrict__ in,
                                                 const float* __restrict__ W,
                                                 const float* __restrict__ bias,
                                                 float* __restrict__ out,
                                                 int K, int ldin, int ldout, int ooff)
{
    __shared__ float in_s[4][1024];
    const int tid = threadIdx.x;
    const int r0 = blockIdx.x * 4;
    for (int idx = tid; idx < 4 * K; idx += 512) {
        int rr = idx / K, kk = idx - rr * K;
        in_s[rr][kk] = in[(r0 + rr) * ldin + kk];
    }
    __syncthreads();
    float a[4] = {0.f, 0.f, 0.f, 0.f};
#pragma unroll 4
    for (int k = 0; k < K; k++) {
        float w = W[k * 512 + tid];
#pragma unroll
        for (int rr = 0; rr < 4; rr++) a[rr] += in_s[rr][k] * w;
    }
    float b = bias[tid];
#pragma unroll
    for (int rr = 0; rr < 4; rr++)
        out[(r0 + rr) * ldout + ooff + tid] = fmaxf(a[rr] + b, 0.f);
}

// ---------------- logits ----------------------------------------------------
__global__ __launch_bounds__(64) void logits_k(const float* __restrict__ hid,
                                               const float* __restrict__ W,
                                               const float* __restrict__ b,
                                               float* __restrict__ out)
{
    __shared__ float s0[64], s1[64];
    int r = blockIdx.x, tid = threadIdx.x;
    float a0 = 0.f, a1 = 0.f;
    for (int k = tid; k < 512; k += 64) {
        float h = hid[r * 512 + k];
        a0 += h * W[k * 2];
        a1 += h * W[k * 2 + 1];
    }
    s0[tid] = a0; s1[tid] = a1;
    __syncthreads();
    if (tid < 2) {
        const float* ss = tid ? s1 : s0;
        float s = 0.f;
        for (int i = 0; i < 64; i++) s += ss[i];
        out[r * 2 + tid] = s + b[tid];
    }
}

extern "C" void kernel_launch(void* const* d_in, const int* in_sizes, int n_in,
                              void* d_out, int out_size)
{
    const float* x1   = (const float*)d_in[0];
    const float* x2   = (const float*)d_in[1];
    const float* em1  = (const float*)d_in[2];
    const float* em2  = (const float*)d_in[3];
    const float* Wl1  = (const float*)d_in[4];
    const float* Wl2  = (const float*)d_in[5];
    const float* lng1 = (const float*)d_in[6];
    const float* lnb1 = (const float*)d_in[7];
    const float* lng2 = (const float*)d_in[8];
    const float* lnb2 = (const float*)d_in[9];
    const float* v1   = (const float*)d_in[10];
    const float* Wo1  = (const float*)d_in[11];
    const float* bo1  = (const float*)d_in[12];
    const float* v2   = (const float*)d_in[13];
    const float* Wo2  = (const float*)d_in[14];
    const float* bo2  = (const float*)d_in[15];
    const float* W_h  = (const float*)d_in[16];
    const float* b_h  = (const float*)d_in[17];
    const float* Wout = (const float*)d_in[18];
    const float* bout = (const float*)d_in[19];
    float* out = (float*)d_out;

    float *xz1, *xz2, *hb1, *hb2, *c1, *c2, *acat, *hid;
    __nv_bfloat16 *bt1h, *bt1l, *bt2h, *bt2l, *wt1h, *wt1l, *wt2h, *wt2l;
    __nv_bfloat16 *x1h, *x1l, *x2h, *x2l, *e1h, *e1l, *e2h, *e2l;
    cudaGetSymbolAddress((void**)&xz1, g_xz1);
    cudaGetSymbolAddress((void**)&xz2, g_xz2);
    cudaGetSymbolAddress((void**)&hb1, g_hb1);
    cudaGetSymbolAddress((void**)&hb2, g_hb2);
    cudaGetSymbolAddress((void**)&c1,  g_ctx1);
    cudaGetSymbolAddress((void**)&c2,  g_ctx2);
    cudaGetSymbolAddress((void**)&acat, g_acat);
    cudaGetSymbolAddress((void**)&hid,  g_hidden);
    cudaGetSymbolAddress((void**)&bt1h, g_bt1h);
    cudaGetSymbolAddress((void**)&bt1l, g_bt1l);
    cudaGetSymbolAddress((void**)&bt2h, g_bt2h);
    cudaGetSymbolAddress((void**)&bt2l, g_bt2l);
    cudaGetSymbolAddress((void**)&wt1h, g_wt1h);
    cudaGetSymbolAddress((void**)&wt1l, g_wt1l);
    cudaGetSymbolAddress((void**)&wt2h, g_wt2h);
    cudaGetSymbolAddress((void**)&wt2l, g_wt2l);
    cudaGetSymbolAddress((void**)&x1h, g_x1h);
    cudaGetSymbolAddress((void**)&x1l, g_x1l);
    cudaGetSymbolAddress((void**)&x2h, g_x2h);
    cudaGetSymbolAddress((void**)&x2l, g_x2l);
    cudaGetSymbolAddress((void**)&e1h, g_e1h);
    cudaGetSymbolAddress((void**)&e1l, g_e1l);
    cudaGetSymbolAddress((void**)&e2h, g_e2h);
    cudaGetSymbolAddress((void**)&e2l, g_e2l);

    cudaFuncSetAttribute(hgemm3_k, cudaFuncAttributeMaxDynamicSharedMemorySize, HG_SMEM);

    // launch 1: unified prep
    prep_u_k<<<dim3(256, 16, 6), dim3(32, 8)>>>(
        em1, em2, Wl1, Wl2, x1, x2,
        bt1h, bt1l, bt2h, bt2l, wt1h, wt1l, wt2h, wt2l,
        x1h, x1l, x2h, x2l);

    // launch 2: K1 merged, e = x @ embed, bf16 hi/lo out
    hgemm3_k<<<dim3(NPAD / 128, MB / 128, 2), 128, HG_SMEM>>>(
        x1h, x1l, x2h, x2l, bt1h, bt1l, bt2h, bt2l,
        (float*)0, (float*)0, e1h, e1l, e2h, e2l,
        KPAD, KPAD / 32, NPAD, 1);

    // launch 3: K2 merged, xz = e @ W_x, fp32 out
    hgemm3_k<<<dim3(HX / 128, MB / 128, 2), 128, HG_SMEM>>>(
        e1h, e1l, e2h, e2l, wt1h, wt1l, wt2h, wt2l,
        xz1, xz2, (__nv_bfloat16*)0, (__nv_bfloat16*)0, (__nv_bfloat16*)0, (__nv_bfloat16*)0,
        KPADW, KPADW / 32, HX, 0);

    // launch 4 (profiled): LSTM recurrence
    lstm_k<<<128, 512>>>(xz1, xz2, Wl1, Wl2, lng1, lnb1, lng2, lnb2,
                         v1, v2, hb1, hb2, c1, c2);

    fc_a_k<<<dim3(32, 1, 2), 512>>>(c1, c2, Wo1, Wo2, bo1, bo2, acat);
    fc_relu_k<<<32, 512>>>(acat, W_h, b_h, hid, 1024, 1024, 512, 0);
    logits_k<<<128, 64>>>(hid, Wout, bout, out);
}